// round 2
// baseline (speedup 1.0000x reference)
#include <cuda_runtime.h>
#include <math.h>

#define N_NODES 50000
#define N_EDGES 1250000
#define D 64
#define L 3

// Scratch (allocation-free): aggregation buffer + current hidden state.
__device__ float g_agg[N_NODES * D];
__device__ float g_h[N_NODES * D];

// ---------------------------------------------------------------------------
// Zero the aggregation buffer (12.8 MB), vectorized.
__global__ void zero_agg_kernel() {
    int i = blockIdx.x * blockDim.x + threadIdx.x;
    if (i < N_NODES * D / 4) {
        ((float4*)g_agg)[i] = make_float4(0.f, 0.f, 0.f, 0.f);
    }
}

// ---------------------------------------------------------------------------
// Copy input h into out[:, 0:64] (row stride 256 floats).
__global__ void copy_h_kernel(const float* __restrict__ h, float* __restrict__ out) {
    int i = blockIdx.x * blockDim.x + threadIdx.x;  // over N_NODES*16 float4 chunks
    if (i >= N_NODES * 16) return;
    int node = i >> 4;
    int c = i & 15;
    float4 v = ((const float4*)h)[i];
    ((float4*)(out + (size_t)node * 256))[c] = v;
}

// ---------------------------------------------------------------------------
// Edge scatter: agg[dst] += h[src] * w.
// 16 threads per edge, each owning one float4 (coalesced 256B per edge group).
__global__ void scatter_kernel(const float* __restrict__ hext,
                               const float* __restrict__ ew,
                               const int* __restrict__ src,
                               const int* __restrict__ dst,
                               int use_ext) {
    int idx = blockIdx.x * blockDim.x + threadIdx.x;
    int e = idx >> 4;
    if (e >= N_EDGES) return;
    int c = idx & 15;

    const float4* h4 = use_ext ? (const float4*)hext : (const float4*)g_h;

    int s = src[e];
    int d = dst[e];
    float w = ew[e];

    float4 v = h4[s * 16 + c];
    float* p = g_agg + (size_t)d * 64 + c * 4;
    atomicAdd(p + 0, v.x * w);
    atomicAdd(p + 1, v.y * w);
    atomicAdd(p + 2, v.z * w);
    atomicAdd(p + 3, v.w * w);
}

// ---------------------------------------------------------------------------
// Dense transform: h_next = agg @ W + b, optional tanh.
// Writes both g_h (next layer input) and the output slab column block.
// One warp per node row; W (64x64) staged in shared memory.
__global__ void gemm_bias_act_kernel(const float* __restrict__ W,
                                     const float* __restrict__ b,
                                     float* __restrict__ out,
                                     int out_col_off,
                                     int do_tanh) {
    __shared__ float Ws[64 * 64];
    __shared__ float bsh[64];

    int t = threadIdx.x;  // 256 threads = 8 warps
    #pragma unroll
    for (int i = t; i < 64 * 64; i += 256) Ws[i] = W[i];
    if (t < 64) bsh[t] = b[t];
    __syncthreads();

    int warp = t >> 5;
    int lane = t & 31;
    int row = blockIdx.x * 8 + warp;
    if (row >= N_NODES) return;

    // Each lane holds 2 consecutive elements of the agg row.
    float2 a2 = ((const float2*)(g_agg + (size_t)row * 64))[lane];

    float acc0 = bsh[lane];
    float acc1 = bsh[lane + 32];

    #pragma unroll
    for (int k = 0; k < 64; k++) {
        float a = __shfl_sync(0xffffffffu, (k & 1) ? a2.y : a2.x, k >> 1);
        acc0 += a * Ws[k * 64 + lane];
        acc1 += a * Ws[k * 64 + lane + 32];
    }

    if (do_tanh) {
        acc0 = tanhf(acc0);
        acc1 = tanhf(acc1);
    }

    g_h[(size_t)row * 64 + lane]      = acc0;
    g_h[(size_t)row * 64 + lane + 32] = acc1;

    float* orow = out + (size_t)row * 256 + out_col_off;
    orow[lane]      = acc0;
    orow[lane + 32] = acc1;
}

// ---------------------------------------------------------------------------
extern "C" void kernel_launch(void* const* d_in, const int* in_sizes, int n_in,
                              void* d_out, int out_size) {
    const float* h   = (const float*)d_in[0];  // [N, 64]
    const float* ew  = (const float*)d_in[1];  // [E]
    const float* Ws  = (const float*)d_in[2];  // [3, 64, 64]
    const float* bs  = (const float*)d_in[3];  // [3, 64]
    const int*   src = (const int*)d_in[4];    // [E]
    const int*   dst = (const int*)d_in[5];    // [E]
    float*       out = (float*)d_out;          // [N, 256]

    // out[:, 0:64] = h
    copy_h_kernel<<<(N_NODES * 16 + 255) / 256, 256>>>(h, out);

    for (int l = 0; l < L; l++) {
        zero_agg_kernel<<<(N_NODES * D / 4 + 255) / 256, 256>>>();

        scatter_kernel<<<(N_EDGES * 16 + 255) / 256, 256>>>(
            h, ew, src, dst, (l == 0) ? 1 : 0);

        gemm_bias_act_kernel<<<N_NODES / 8, 256>>>(
            Ws + l * 64 * 64, bs + l * 64, out, (l + 1) * 64, (l < L - 1) ? 1 : 0);
    }
}

// round 3
// speedup vs baseline: 2.3576x; 2.3576x over previous
#include <cuda_runtime.h>
#include <math.h>

#define N_NODES 50000
#define N_EDGES 1250000
#define D 64
#define L 3

// Scratch (allocation-free): aggregation buffer + current hidden state.
__device__ float g_agg[N_NODES * D];
__device__ float g_h[N_NODES * D];

// ---------------------------------------------------------------------------
// Zero the aggregation buffer (12.8 MB), vectorized.
__global__ void zero_agg_kernel() {
    int i = blockIdx.x * blockDim.x + threadIdx.x;
    if (i < N_NODES * D / 4) {
        ((float4*)g_agg)[i] = make_float4(0.f, 0.f, 0.f, 0.f);
    }
}

// ---------------------------------------------------------------------------
// Copy input h into out[:, 0:64] (row stride 256 floats).
__global__ void copy_h_kernel(const float* __restrict__ h, float* __restrict__ out) {
    int i = blockIdx.x * blockDim.x + threadIdx.x;  // over N_NODES*16 float4 chunks
    if (i >= N_NODES * 16) return;
    int node = i >> 4;
    int c = i & 15;
    float4 v = ((const float4*)h)[i];
    ((float4*)(out + (size_t)node * 256))[c] = v;
}

// ---------------------------------------------------------------------------
// Edge scatter: agg[dst] += h[src] * w.
// 16 threads per edge, each owning one float4; one red.global.add.v4.f32 per
// thread (16B atomic transaction instead of 4x 4B).
__global__ void scatter_kernel(const float* __restrict__ hext,
                               const float* __restrict__ ew,
                               const int* __restrict__ src,
                               const int* __restrict__ dst,
                               int use_ext) {
    int idx = blockIdx.x * blockDim.x + threadIdx.x;
    int e = idx >> 4;
    if (e >= N_EDGES) return;
    int c = idx & 15;

    const float4* h4 = use_ext ? (const float4*)hext : (const float4*)g_h;

    int s = src[e];
    int d = dst[e];
    float w = ew[e];

    float4 v = h4[s * 16 + c];
    float* p = g_agg + (size_t)d * 64 + c * 4;
    asm volatile("red.global.add.v4.f32 [%0], {%1, %2, %3, %4};"
                 :: "l"(p), "f"(v.x * w), "f"(v.y * w), "f"(v.z * w), "f"(v.w * w)
                 : "memory");
}

// ---------------------------------------------------------------------------
// Dense transform: h_next = agg @ W + b, optional tanh.
// 64-row tile per block (256 threads). A staged transposed in smem, W staged
// row-major. Each thread computes a 4x4 register tile:
//   per k-step: 1 LDS.128 (A rows) + 1 LDS.128 (W cols) + 16 FFMA.
__global__ void gemm_bias_act_kernel(const float* __restrict__ W,
                                     const float* __restrict__ b,
                                     float* __restrict__ out,
                                     int out_col_off,
                                     int do_tanh) {
    __shared__ __align__(16) float AsT[64][68];   // [k][row], stride 68 keeps 16B align
    __shared__ __align__(16) float Wsm[64 * 64];  // [k][col]
    __shared__ float bsh[64];

    int t = threadIdx.x;  // 256 threads
    int rowBase = blockIdx.x * 64;

    #pragma unroll
    for (int i = t; i < 64 * 64; i += 256) Wsm[i] = W[i];
    if (t < 64) bsh[t] = b[t];

    // Load A tile transposed: AsT[k][row] = agg[rowBase+row][k]
    #pragma unroll
    for (int i = 0; i < 4; i++) {
        int idx = t + i * 256;          // 0..1023
        int row = idx >> 4;             // 0..63
        int c4  = idx & 15;             // float4 column chunk
        int grow = rowBase + row;
        float4 v = (grow < N_NODES) ? ((const float4*)g_agg)[grow * 16 + c4]
                                    : make_float4(0.f, 0.f, 0.f, 0.f);
        AsT[c4 * 4 + 0][row] = v.x;
        AsT[c4 * 4 + 1][row] = v.y;
        AsT[c4 * 4 + 2][row] = v.z;
        AsT[c4 * 4 + 3][row] = v.w;
    }
    __syncthreads();

    int tx = t & 15;   // column group: cols tx*4 .. tx*4+3
    int ty = t >> 4;   // row group:    rows ty*4 .. ty*4+3

    float acc[4][4];
    #pragma unroll
    for (int i = 0; i < 4; i++)
        #pragma unroll
        for (int j = 0; j < 4; j++)
            acc[i][j] = bsh[tx * 4 + j];

    #pragma unroll 16
    for (int k = 0; k < 64; k++) {
        float4 a = *(const float4*)&AsT[k][ty * 4];
        float4 w = *(const float4*)&Wsm[k * 64 + tx * 4];
        acc[0][0] += a.x * w.x; acc[0][1] += a.x * w.y; acc[0][2] += a.x * w.z; acc[0][3] += a.x * w.w;
        acc[1][0] += a.y * w.x; acc[1][1] += a.y * w.y; acc[1][2] += a.y * w.z; acc[1][3] += a.y * w.w;
        acc[2][0] += a.z * w.x; acc[2][1] += a.z * w.y; acc[2][2] += a.z * w.z; acc[2][3] += a.z * w.w;
        acc[3][0] += a.w * w.x; acc[3][1] += a.w * w.y; acc[3][2] += a.w * w.z; acc[3][3] += a.w * w.w;
    }

    #pragma unroll
    for (int i = 0; i < 4; i++) {
        int grow = rowBase + ty * 4 + i;
        if (grow >= N_NODES) continue;
        float4 r = make_float4(acc[i][0], acc[i][1], acc[i][2], acc[i][3]);
        if (do_tanh) {
            r.x = tanhf(r.x); r.y = tanhf(r.y); r.z = tanhf(r.z); r.w = tanhf(r.w);
        }
        *(float4*)(g_h + (size_t)grow * 64 + tx * 4) = r;
        *(float4*)(out + (size_t)grow * 256 + out_col_off + tx * 4) = r;
    }
}

// ---------------------------------------------------------------------------
extern "C" void kernel_launch(void* const* d_in, const int* in_sizes, int n_in,
                              void* d_out, int out_size) {
    const float* h   = (const float*)d_in[0];  // [N, 64]
    const float* ew  = (const float*)d_in[1];  // [E]
    const float* Ws  = (const float*)d_in[2];  // [3, 64, 64]
    const float* bs  = (const float*)d_in[3];  // [3, 64]
    const int*   src = (const int*)d_in[4];    // [E]
    const int*   dst = (const int*)d_in[5];    // [E]
    float*       out = (float*)d_out;          // [N, 256]

    // out[:, 0:64] = h
    copy_h_kernel<<<(N_NODES * 16 + 255) / 256, 256>>>(h, out);

    for (int l = 0; l < L; l++) {
        zero_agg_kernel<<<(N_NODES * D / 4 + 255) / 256, 256>>>();

        scatter_kernel<<<(N_EDGES * 16 + 255) / 256, 256>>>(
            h, ew, src, dst, (l == 0) ? 1 : 0);

        gemm_bias_act_kernel<<<(N_NODES + 63) / 64, 256>>>(
            Ws + l * 64 * 64, bs + l * 64, out, (l + 1) * 64, (l < L - 1) ? 1 : 0);
    }
}

// round 4
// speedup vs baseline: 2.5776x; 1.0933x over previous
#include <cuda_runtime.h>
#include <math.h>

#define N_NODES 50000
#define N_EDGES 1250000
#define D 64
#define L 3

// Scratch (allocation-free).
__device__ float g_agg[N_NODES * D];
__device__ float g_h[N_NODES * D];
__device__ int   g_cnt[N_NODES];
__device__ int   g_off[N_NODES + 1];
__device__ int   g_cursor[N_NODES];
__device__ int2  g_csr[N_EDGES];     // .x = src node, .y = weight bits

// ---------------------------------------------------------------------------
// Copy input h into out[:, 0:64]; also zero the CSR counters.
__global__ void copy_h_zero_cnt_kernel(const float* __restrict__ h,
                                       float* __restrict__ out) {
    int i = blockIdx.x * blockDim.x + threadIdx.x;
    if (i < N_NODES) g_cnt[i] = 0;
    if (i >= N_NODES * 16) return;
    int node = i >> 4;
    int c = i & 15;
    float4 v = ((const float4*)h)[i];
    ((float4*)(out + (size_t)node * 256))[c] = v;
}

// ---------------------------------------------------------------------------
// CSR build pass 1: count in-degree per dst node.
__global__ void count_kernel(const int* __restrict__ dst) {
    int e = blockIdx.x * blockDim.x + threadIdx.x;
    if (e >= N_EDGES) return;
    atomicAdd(&g_cnt[dst[e]], 1);
}

// ---------------------------------------------------------------------------
// CSR build pass 2: exclusive prefix scan of counts (single block, 1024 thr).
__global__ void scan_kernel() {
    __shared__ int partial[1024];
    const int CHUNK = (N_NODES + 1023) / 1024;  // 49
    int t = threadIdx.x;
    int start = t * CHUNK;

    int sum = 0;
    for (int i = 0; i < CHUNK; i++) {
        int idx = start + i;
        if (idx < N_NODES) sum += g_cnt[idx];
    }
    partial[t] = sum;
    __syncthreads();

    // Hillis-Steele inclusive scan over 1024 partials.
    for (int off = 1; off < 1024; off <<= 1) {
        int v = (t >= off) ? partial[t - off] : 0;
        __syncthreads();
        partial[t] += v;
        __syncthreads();
    }

    int run = (t == 0) ? 0 : partial[t - 1];
    for (int i = 0; i < CHUNK; i++) {
        int idx = start + i;
        if (idx < N_NODES) {
            g_off[idx] = run;
            g_cursor[idx] = run;
            run += g_cnt[idx];
        }
    }
    if (t == 0) g_off[N_NODES] = partial[1023];
}

// ---------------------------------------------------------------------------
// CSR build pass 3: scatter edges into dst-sorted order.
__global__ void fill_kernel(const int* __restrict__ src,
                            const int* __restrict__ dst,
                            const float* __restrict__ ew) {
    int e = blockIdx.x * blockDim.x + threadIdx.x;
    if (e >= N_EDGES) return;
    int d = dst[e];
    int pos = atomicAdd(&g_cursor[d], 1);
    g_csr[pos] = make_int2(src[e], __float_as_int(ew[e]));
}

// ---------------------------------------------------------------------------
// Pull aggregation: agg[n] = sum_{edges into n} h[src] * w. Atomic-free.
// 16 threads per node, each owning one float4 column chunk.
__global__ void gather_kernel(const float* __restrict__ hext, int use_ext) {
    int idx = blockIdx.x * blockDim.x + threadIdx.x;
    int node = idx >> 4;
    if (node >= N_NODES) return;
    int c = idx & 15;

    const float4* __restrict__ h4 =
        use_ext ? (const float4*)hext : (const float4*)g_h;

    int beg = g_off[node];
    int end = g_off[node + 1];

    float4 acc = make_float4(0.f, 0.f, 0.f, 0.f);
    int j = beg;
    // Unroll by 2 for MLP on the dependent (csr entry -> h row) load chain.
    for (; j + 2 <= end; j += 2) {
        int2 e0 = g_csr[j];
        int2 e1 = g_csr[j + 1];
        float w0 = __int_as_float(e0.y);
        float w1 = __int_as_float(e1.y);
        float4 v0 = h4[e0.x * 16 + c];
        float4 v1 = h4[e1.x * 16 + c];
        acc.x += v0.x * w0; acc.y += v0.y * w0;
        acc.z += v0.z * w0; acc.w += v0.w * w0;
        acc.x += v1.x * w1; acc.y += v1.y * w1;
        acc.z += v1.z * w1; acc.w += v1.w * w1;
    }
    if (j < end) {
        int2 e0 = g_csr[j];
        float w0 = __int_as_float(e0.y);
        float4 v0 = h4[e0.x * 16 + c];
        acc.x += v0.x * w0; acc.y += v0.y * w0;
        acc.z += v0.z * w0; acc.w += v0.w * w0;
    }

    ((float4*)g_agg)[node * 16 + c] = acc;
}

// ---------------------------------------------------------------------------
// Dense transform: h_next = agg @ W + b, optional tanh. (unchanged from R3)
__global__ void gemm_bias_act_kernel(const float* __restrict__ W,
                                     const float* __restrict__ b,
                                     float* __restrict__ out,
                                     int out_col_off,
                                     int do_tanh) {
    __shared__ __align__(16) float AsT[64][68];
    __shared__ __align__(16) float Wsm[64 * 64];
    __shared__ float bsh[64];

    int t = threadIdx.x;  // 256 threads
    int rowBase = blockIdx.x * 64;

    #pragma unroll
    for (int i = t; i < 64 * 64; i += 256) Wsm[i] = W[i];
    if (t < 64) bsh[t] = b[t];

    #pragma unroll
    for (int i = 0; i < 4; i++) {
        int idx = t + i * 256;
        int row = idx >> 4;
        int c4  = idx & 15;
        int grow = rowBase + row;
        float4 v = (grow < N_NODES) ? ((const float4*)g_agg)[grow * 16 + c4]
                                    : make_float4(0.f, 0.f, 0.f, 0.f);
        AsT[c4 * 4 + 0][row] = v.x;
        AsT[c4 * 4 + 1][row] = v.y;
        AsT[c4 * 4 + 2][row] = v.z;
        AsT[c4 * 4 + 3][row] = v.w;
    }
    __syncthreads();

    int tx = t & 15;
    int ty = t >> 4;

    float acc[4][4];
    #pragma unroll
    for (int i = 0; i < 4; i++)
        #pragma unroll
        for (int j = 0; j < 4; j++)
            acc[i][j] = bsh[tx * 4 + j];

    #pragma unroll 16
    for (int k = 0; k < 64; k++) {
        float4 a = *(const float4*)&AsT[k][ty * 4];
        float4 w = *(const float4*)&Wsm[k * 64 + tx * 4];
        acc[0][0] += a.x * w.x; acc[0][1] += a.x * w.y; acc[0][2] += a.x * w.z; acc[0][3] += a.x * w.w;
        acc[1][0] += a.y * w.x; acc[1][1] += a.y * w.y; acc[1][2] += a.y * w.z; acc[1][3] += a.y * w.w;
        acc[2][0] += a.z * w.x; acc[2][1] += a.z * w.y; acc[2][2] += a.z * w.z; acc[2][3] += a.z * w.w;
        acc[3][0] += a.w * w.x; acc[3][1] += a.w * w.y; acc[3][2] += a.w * w.z; acc[3][3] += a.w * w.w;
    }

    #pragma unroll
    for (int i = 0; i < 4; i++) {
        int grow = rowBase + ty * 4 + i;
        if (grow >= N_NODES) continue;
        float4 r = make_float4(acc[i][0], acc[i][1], acc[i][2], acc[i][3]);
        if (do_tanh) {
            r.x = tanhf(r.x); r.y = tanhf(r.y); r.z = tanhf(r.z); r.w = tanhf(r.w);
        }
        *(float4*)(g_h + (size_t)grow * 64 + tx * 4) = r;
        *(float4*)(out + (size_t)grow * 256 + out_col_off + tx * 4) = r;
    }
}

// ---------------------------------------------------------------------------
extern "C" void kernel_launch(void* const* d_in, const int* in_sizes, int n_in,
                              void* d_out, int out_size) {
    const float* h   = (const float*)d_in[0];  // [N, 64]
    const float* ew  = (const float*)d_in[1];  // [E]
    const float* Ws  = (const float*)d_in[2];  // [3, 64, 64]
    const float* bs  = (const float*)d_in[3];  // [3, 64]
    const int*   src = (const int*)d_in[4];    // [E]
    const int*   dst = (const int*)d_in[5];    // [E]
    float*       out = (float*)d_out;          // [N, 256]

    // out[:, 0:64] = h; zero degree counters.
    copy_h_zero_cnt_kernel<<<(N_NODES * 16 + 255) / 256, 256>>>(h, out);

    // Build CSR (by dst) once — graph is constant across layers.
    count_kernel<<<(N_EDGES + 255) / 256, 256>>>(dst);
    scan_kernel<<<1, 1024>>>();
    fill_kernel<<<(N_EDGES + 255) / 256, 256>>>(src, dst, ew);

    for (int l = 0; l < L; l++) {
        gather_kernel<<<(N_NODES * 16 + 255) / 256, 256>>>(h, (l == 0) ? 1 : 0);
        gemm_bias_act_kernel<<<(N_NODES + 63) / 64, 256>>>(
            Ws + l * 64 * 64, bs + l * 64, out, (l + 1) * 64, (l < L - 1) ? 1 : 0);
    }
}